// round 1
// baseline (speedup 1.0000x reference)
#include <cuda_runtime.h>
#include <math.h>

#define B_SZ  2
#define S_LEN 2048
#define D_DIM 1024
#define H_NUM 16
#define DKH   64

// Scratch (allocation-free rule: __device__ globals)
__device__ float g_Q[B_SZ * S_LEN * D_DIM];
__device__ float g_K[B_SZ * S_LEN * D_DIM];
__device__ float g_V[B_SZ * S_LEN * D_DIM];
__device__ float g_X[B_SZ * S_LEN * D_DIM];

// ---------------------------------------------------------------------------
// GEMM (NT): C[M,N] = A[M,K] @ W[N,K]^T      (torch Linear: y = x @ W.T)
// 128x128 tile, BK=16, 256 threads, 8x8 per-thread register tile.
// ---------------------------------------------------------------------------
constexpr int GBM = 128, GBN = 128, GBK = 16;

__global__ __launch_bounds__(256, 2)
void gemm_nt(const float* __restrict__ A, const float* __restrict__ W,
             float* __restrict__ C, int M, int N, int K)
{
    __shared__ float As[GBK][GBM + 4];
    __shared__ float Bs[GBK][GBN + 4];

    const int tid = threadIdx.x;
    const int tx  = tid & 15;   // col group (0..15)
    const int ty  = tid >> 4;   // row group (0..15)
    const int m0  = blockIdx.y * GBM;
    const int n0  = blockIdx.x * GBN;

    // load mapping: 128 rows x 16 k per tile; each thread: 1 row, 8 floats (2 float4)
    const int lrow = tid >> 1;        // 0..127
    const int lcol = (tid & 1) * 8;   // 0 or 8

    float acc[8][8];
#pragma unroll
    for (int i = 0; i < 8; i++)
#pragma unroll
        for (int j = 0; j < 8; j++) acc[i][j] = 0.f;

    for (int k0 = 0; k0 < K; k0 += GBK) {
        const float* ap = A + (size_t)(m0 + lrow) * K + k0 + lcol;
        float4 a0 = *(const float4*)(ap);
        float4 a1 = *(const float4*)(ap + 4);
        const float* wp = W + (size_t)(n0 + lrow) * K + k0 + lcol;
        float4 b0 = *(const float4*)(wp);
        float4 b1 = *(const float4*)(wp + 4);

        As[lcol + 0][lrow] = a0.x; As[lcol + 1][lrow] = a0.y;
        As[lcol + 2][lrow] = a0.z; As[lcol + 3][lrow] = a0.w;
        As[lcol + 4][lrow] = a1.x; As[lcol + 5][lrow] = a1.y;
        As[lcol + 6][lrow] = a1.z; As[lcol + 7][lrow] = a1.w;
        Bs[lcol + 0][lrow] = b0.x; Bs[lcol + 1][lrow] = b0.y;
        Bs[lcol + 2][lrow] = b0.z; Bs[lcol + 3][lrow] = b0.w;
        Bs[lcol + 4][lrow] = b1.x; Bs[lcol + 5][lrow] = b1.y;
        Bs[lcol + 6][lrow] = b1.z; Bs[lcol + 7][lrow] = b1.w;
        __syncthreads();

#pragma unroll
        for (int k = 0; k < GBK; k++) {
            float4 ra0 = *(const float4*)&As[k][ty * 8];
            float4 ra1 = *(const float4*)&As[k][ty * 8 + 4];
            float4 rb0 = *(const float4*)&Bs[k][tx * 8];
            float4 rb1 = *(const float4*)&Bs[k][tx * 8 + 4];
            float ra[8] = {ra0.x, ra0.y, ra0.z, ra0.w, ra1.x, ra1.y, ra1.z, ra1.w};
            float rb[8] = {rb0.x, rb0.y, rb0.z, rb0.w, rb1.x, rb1.y, rb1.z, rb1.w};
#pragma unroll
            for (int i = 0; i < 8; i++)
#pragma unroll
                for (int j = 0; j < 8; j++)
                    acc[i][j] += ra[i] * rb[j];
        }
        __syncthreads();
    }

#pragma unroll
    for (int i = 0; i < 8; i++) {
        float* cp = C + (size_t)(m0 + ty * 8 + i) * N + n0 + tx * 8;
        float4 v0 = make_float4(acc[i][0], acc[i][1], acc[i][2], acc[i][3]);
        float4 v1 = make_float4(acc[i][4], acc[i][5], acc[i][6], acc[i][7]);
        *(float4*)(cp)     = v0;
        *(float4*)(cp + 4) = v1;
    }
}

// ---------------------------------------------------------------------------
// Flash attention, causal. One CTA = one (b, h, 64-row q block).
// 256 threads = 16 (tc) x 16 (tr). Each thread: 4 rows x 4 cols register tile
// for both the score (QK^T) and PV phases. Online softmax; row reductions via
// shfl over the 16 tc lanes.
// smem: Qs, Ks, Vs, Ps each 64 x 68 fp32 (row stride 68 -> 16B aligned rows).
// ---------------------------------------------------------------------------
constexpr int FS = 68;

__global__ __launch_bounds__(256)
void flash_attn(const float* __restrict__ Qp, const float* __restrict__ Kp,
                const float* __restrict__ Vp, float* __restrict__ Op)
{
    extern __shared__ float sm[];
    float* Qs = sm;
    float* Ks = Qs + 64 * FS;
    float* Vs = Ks + 64 * FS;
    float* Ps = Vs + 64 * FS;

    const int tid = threadIdx.x;
    const int tc  = tid & 15;    // 0..15 : col lane
    const int tr  = tid >> 4;    // 0..15 : row group (rows tr*4 .. tr*4+3)
    const int qb  = blockIdx.x;  // q block (0..31)
    const int h   = blockIdx.y;
    const int b   = blockIdx.z;

    const size_t head_base = (size_t)b * S_LEN * D_DIM + (size_t)h * DKH;

    // tile-load mapping: row lr (0..63), 16 consecutive cols starting at lc
    const int lr = tid >> 2;
    const int lc = (tid & 3) * 16;

    { // load Q tile
        const float* src = Qp + head_base + (size_t)(qb * 64 + lr) * D_DIM + lc;
        float4 v0 = *(const float4*)(src);
        float4 v1 = *(const float4*)(src + 4);
        float4 v2 = *(const float4*)(src + 8);
        float4 v3 = *(const float4*)(src + 12);
        float* dst = Qs + lr * FS + lc;
        *(float4*)(dst)      = v0;
        *(float4*)(dst + 4)  = v1;
        *(float4*)(dst + 8)  = v2;
        *(float4*)(dst + 12) = v3;
    }

    float m_i[4], l_i[4], o[4][4];
#pragma unroll
    for (int i = 0; i < 4; i++) {
        m_i[i] = -1e30f; l_i[i] = 0.f;
#pragma unroll
        for (int c = 0; c < 4; c++) o[i][c] = 0.f;
    }

    for (int kb = 0; kb <= qb; kb++) {
        __syncthreads();  // previous iteration done with Ks/Vs/Ps
        { // load K and V tiles
            const float* ks = Kp + head_base + (size_t)(kb * 64 + lr) * D_DIM + lc;
            const float* vs = Vp + head_base + (size_t)(kb * 64 + lr) * D_DIM + lc;
            float* kd = Ks + lr * FS + lc;
            float* vd = Vs + lr * FS + lc;
            float4 k0 = *(const float4*)(ks);
            float4 k1 = *(const float4*)(ks + 4);
            float4 k2 = *(const float4*)(ks + 8);
            float4 k3 = *(const float4*)(ks + 12);
            *(float4*)(kd) = k0; *(float4*)(kd + 4) = k1;
            *(float4*)(kd + 8) = k2; *(float4*)(kd + 12) = k3;
            float4 v0 = *(const float4*)(vs);
            float4 v1 = *(const float4*)(vs + 4);
            float4 v2 = *(const float4*)(vs + 8);
            float4 v3 = *(const float4*)(vs + 12);
            *(float4*)(vd) = v0; *(float4*)(vd + 4) = v1;
            *(float4*)(vd + 8) = v2; *(float4*)(vd + 12) = v3;
        }
        __syncthreads();

        // ---- scores: sc[i][jj] = Q[row tr*4+i] . K[col tc+16*jj] ----
        float sc[4][4];
#pragma unroll
        for (int i = 0; i < 4; i++)
#pragma unroll
            for (int jj = 0; jj < 4; jj++) sc[i][jj] = 0.f;

#pragma unroll 4
        for (int c = 0; c < 64; c += 4) {
            float4 qv[4], kv[4];
#pragma unroll
            for (int i = 0; i < 4; i++)
                qv[i] = *(const float4*)&Qs[(tr * 4 + i) * FS + c];
#pragma unroll
            for (int jj = 0; jj < 4; jj++)
                kv[jj] = *(const float4*)&Ks[(tc + 16 * jj) * FS + c];
#pragma unroll
            for (int i = 0; i < 4; i++)
#pragma unroll
                for (int jj = 0; jj < 4; jj++) {
                    sc[i][jj] += qv[i].x * kv[jj].x;
                    sc[i][jj] += qv[i].y * kv[jj].y;
                    sc[i][jj] += qv[i].z * kv[jj].z;
                    sc[i][jj] += qv[i].w * kv[jj].w;
                }
        }

        const bool diag = (kb == qb);
        // ---- per-row online softmax ----
#pragma unroll
        for (int i = 0; i < 4; i++) {
            const int rloc = tr * 4 + i;
            float mx = -1e30f;
#pragma unroll
            for (int jj = 0; jj < 4; jj++) {
                float s = sc[i][jj] * 0.125f;  // 1/sqrt(dk=64)
                if (diag && (tc + 16 * jj) > rloc) s = -1e30f;
                sc[i][jj] = s;
                mx = fmaxf(mx, s);
            }
            mx = fmaxf(mx, __shfl_xor_sync(0xffffffffu, mx, 1));
            mx = fmaxf(mx, __shfl_xor_sync(0xffffffffu, mx, 2));
            mx = fmaxf(mx, __shfl_xor_sync(0xffffffffu, mx, 4));
            mx = fmaxf(mx, __shfl_xor_sync(0xffffffffu, mx, 8));
            const float mn = fmaxf(m_i[i], mx);
            const float alpha = __expf(m_i[i] - mn);
            m_i[i] = mn;
            float ls = 0.f;
#pragma unroll
            for (int jj = 0; jj < 4; jj++) {
                float p = __expf(sc[i][jj] - mn);
                ls += p;
                Ps[rloc * FS + tc + 16 * jj] = p;
            }
            ls += __shfl_xor_sync(0xffffffffu, ls, 1);
            ls += __shfl_xor_sync(0xffffffffu, ls, 2);
            ls += __shfl_xor_sync(0xffffffffu, ls, 4);
            ls += __shfl_xor_sync(0xffffffffu, ls, 8);
            l_i[i] = l_i[i] * alpha + ls;
#pragma unroll
            for (int c = 0; c < 4; c++) o[i][c] *= alpha;
        }
        __syncthreads();  // Ps visible

        // ---- PV: o[i][c] += sum_j P[row, j] * V[j, tc+16c] ----
#pragma unroll 8
        for (int j = 0; j < 64; j++) {
            float pv[4], vv[4];
#pragma unroll
            for (int i = 0; i < 4; i++) pv[i] = Ps[(tr * 4 + i) * FS + j];
#pragma unroll
            for (int c = 0; c < 4; c++) vv[c] = Vs[j * FS + tc + 16 * c];
#pragma unroll
            for (int i = 0; i < 4; i++)
#pragma unroll
                for (int c = 0; c < 4; c++) o[i][c] += pv[i] * vv[c];
        }
    }

    // epilogue: normalize + store (layout already [B,S,H*dk] = [B,S,D])
#pragma unroll
    for (int i = 0; i < 4; i++) {
        const float inv = 1.f / l_i[i];
        const size_t row = head_base + (size_t)(qb * 64 + tr * 4 + i) * D_DIM;
#pragma unroll
        for (int c = 0; c < 4; c++)
            Op[row + tc + 16 * c] = o[i][c] * inv;
    }
}

// ---------------------------------------------------------------------------
// launch
// ---------------------------------------------------------------------------
extern "C" void kernel_launch(void* const* d_in, const int* in_sizes, int n_in,
                              void* d_out, int out_size)
{
    const float* query = (const float*)d_in[0];
    const float* key   = (const float*)d_in[1];
    const float* value = (const float*)d_in[2];
    const float* Wq    = (const float*)d_in[3];
    const float* Wk    = (const float*)d_in[4];
    const float* Wv    = (const float*)d_in[5];
    const float* Wo    = (const float*)d_in[6];
    float* out = (float*)d_out;

    float *qp, *kp, *vp, *xp;
    cudaGetSymbolAddress((void**)&qp, g_Q);
    cudaGetSymbolAddress((void**)&kp, g_K);
    cudaGetSymbolAddress((void**)&vp, g_V);
    cudaGetSymbolAddress((void**)&xp, g_X);

    const int M = B_SZ * S_LEN;  // 4096
    dim3 ggrid(D_DIM / GBN, M / GBM);  // (8, 32)

    gemm_nt<<<ggrid, 256>>>(query, Wq, qp, M, D_DIM, D_DIM);
    gemm_nt<<<ggrid, 256>>>(key,   Wk, kp, M, D_DIM, D_DIM);
    gemm_nt<<<ggrid, 256>>>(value, Wv, vp, M, D_DIM, D_DIM);

    const size_t fsmem = 4 * 64 * FS * sizeof(float);  // 69632 B
    cudaFuncSetAttribute(flash_attn, cudaFuncAttributeMaxDynamicSharedMemorySize,
                         (int)fsmem);
    dim3 fgrid(S_LEN / 64, H_NUM, B_SZ);  // (32, 16, 2)
    flash_attn<<<fgrid, 256, fsmem>>>(qp, kp, vp, xp);

    gemm_nt<<<ggrid, 256>>>(xp, Wo, out, M, D_DIM, D_DIM);
}

// round 3
// speedup vs baseline: 1.5451x; 1.5451x over previous
#include <cuda_runtime.h>
#include <cuda_bf16.h>
#include <math.h>
#include <stdint.h>

#define B_SZ  2
#define S_LEN 2048
#define D_DIM 1024
#define H_NUM 16
#define DKH   64

// Scratch (allocation-free rule: __device__ globals)
__device__ float g_Q[B_SZ * S_LEN * D_DIM];
__device__ float g_K[B_SZ * S_LEN * D_DIM];
__device__ float g_V[B_SZ * S_LEN * D_DIM];
__device__ float g_X[B_SZ * S_LEN * D_DIM];

// ===========================================================================
// helpers (baseline ISA only: ldmatrix sm_75+, mma.sync bf16 sm_80+)
// ===========================================================================
__device__ __forceinline__ uint32_t smem_u32(const void* p) {
    uint32_t a;
    asm("{ .reg .u64 t; cvta.to.shared.u64 t, %1; cvt.u32.u64 %0, t; }"
        : "=r"(a) : "l"(p));
    return a;
}

__device__ __forceinline__ void ldmx4(uint32_t* r, uint32_t addr) {
    asm volatile("ldmatrix.sync.aligned.m8n8.x4.shared.b16 {%0,%1,%2,%3}, [%4];"
                 : "=r"(r[0]), "=r"(r[1]), "=r"(r[2]), "=r"(r[3]) : "r"(addr));
}

__device__ __forceinline__ void mma16816(float* c, const uint32_t* a,
                                         const uint32_t* b) {
    asm volatile(
        "mma.sync.aligned.m16n8k16.row.col.f32.bf16.bf16.f32 "
        "{%0,%1,%2,%3}, {%4,%5,%6,%7}, {%8,%9}, {%0,%1,%2,%3};"
        : "+f"(c[0]), "+f"(c[1]), "+f"(c[2]), "+f"(c[3])
        : "r"(a[0]), "r"(a[1]), "r"(a[2]), "r"(a[3]), "r"(b[0]), "r"(b[1]));
}

// ===========================================================================
// Tensor-core GEMM (NT): C[M,N] = A[M,K] @ W[N,K]^T, fp32 via 3-term bf16
// split (Ah*Bh + Ah*Bl + Al*Bh). CTA tile 128x128, K staged 64 f32 at a time.
// 8 warps: warp_m = wid&1 (2 x 64 rows), warp_n = wid>>1 (4 x 32 cols).
// Each warp: 4x4 grid of m16n8 accum tiles, k16 steps via ldmatrix.x4.
// ===========================================================================
constexpr int SAS     = 72;            // bf16 row stride (64 + 8 pad)
constexpr int SASB    = SAS * 2;       // 144 bytes
constexpr int TILE_B  = 128 * SASB;    // 18432 bytes per tile
constexpr int SM_AHI  = 0;
constexpr int SM_ALO  = TILE_B;
constexpr int SM_BHI  = 2 * TILE_B;
constexpr int SM_BLO  = 3 * TILE_B;
constexpr int SM_GEMM_TOTAL = 4 * TILE_B;   // 73728 B
constexpr int TBK     = 64;            // f32 K per stage
constexpr int STAGES  = D_DIM / TBK;   // 16

__global__ __launch_bounds__(256, 1)
void gemm_mma(const float* __restrict__ A, const float* __restrict__ W,
              float* __restrict__ C, int M, int N, int K)
{
    extern __shared__ char smc[];
    const uint32_t sb = smem_u32(smc);
    const int tid  = threadIdx.x;
    const int wid  = tid >> 5;
    const int lane = tid & 31;
    const int warp_m = wid & 1;
    const int warp_n = wid >> 1;
    const int m0 = blockIdx.y * 128;
    const int n0 = blockIdx.x * 128;

    float acc[4][4][4];
#pragma unroll
    for (int mi = 0; mi < 4; mi++)
#pragma unroll
        for (int ni = 0; ni < 4; ni++)
#pragma unroll
            for (int q = 0; q < 4; q++) acc[mi][ni][q] = 0.f;

    // producer mapping: t<128 -> A tile, t>=128 -> W tile
    const bool isA = tid < 128;
    const int  t   = tid & 127;
    const float* src = isA ? (A + (size_t)m0 * K) : (W + (size_t)n0 * K);
    char* hi_p = smc + (isA ? SM_AHI : SM_BHI);
    char* lo_p = smc + (isA ? SM_ALO : SM_BLO);

    // ldmatrix lane addressing
    const int lr  = lane & 15;            // row within 16-row group
    const int lkb = (lane >> 4) << 4;     // 0 or 16 bytes (k half)

    for (int s = 0; s < STAGES; s++) {
        __syncthreads();   // previous compute done with smem
        // ---- load + split-convert 128x64 f32 -> bf16 hi/lo tiles ----
        const float* s_src = src + s * TBK;
#pragma unroll 4
        for (int i = 0; i < 16; i++) {
            const int chunk = t + (i << 7);
            const int row = chunk >> 4;        // 0..127
            const int ch  = chunk & 15;        // float4 index within row
            const float4 v = *(const float4*)(s_src + (size_t)row * K + (ch << 2));

            __nv_bfloat162 h01 = __float22bfloat162_rn(make_float2(v.x, v.y));
            __nv_bfloat162 h23 = __float22bfloat162_rn(make_float2(v.z, v.w));
            float2 f01 = __bfloat1622float2(h01);
            float2 f23 = __bfloat1622float2(h23);
            __nv_bfloat162 l01 =
                __float22bfloat162_rn(make_float2(v.x - f01.x, v.y - f01.y));
            __nv_bfloat162 l23 =
                __float22bfloat162_rn(make_float2(v.z - f23.x, v.w - f23.y));

            uint2 uh, ul;
            uh.x = *(uint32_t*)&h01; uh.y = *(uint32_t*)&h23;
            ul.x = *(uint32_t*)&l01; ul.y = *(uint32_t*)&l23;

            const uint32_t off = row * SASB + (ch << 3);
            *(uint2*)(hi_p + off) = uh;
            *(uint2*)(lo_p + off) = ul;
        }
        __syncthreads();

        // ---- compute: 4 k16 steps ----
#pragma unroll
        for (int ks = 0; ks < 4; ks++) {
            const uint32_t kb = ks * 32 + lkb;   // byte offset of k within row

            uint32_t ah[4][4], al[4][4];
#pragma unroll
            for (int mi = 0; mi < 4; mi++) {
                const uint32_t row = warp_m * 64 + mi * 16 + lr;
                const uint32_t byte = row * SASB + kb;
                ldmx4(ah[mi], sb + SM_AHI + byte);
                ldmx4(al[mi], sb + SM_ALO + byte);
            }
            uint32_t bh[4][2], bl[4][2];
#pragma unroll
            for (int nb = 0; nb < 2; nb++) {
                const uint32_t row = warp_n * 32 + nb * 16 + lr;
                const uint32_t byte = row * SASB + kb;
                uint32_t r[4];
                ldmx4(r, sb + SM_BHI + byte);
                bh[nb * 2][0] = r[0]; bh[nb * 2 + 1][0] = r[1];
                bh[nb * 2][1] = r[2]; bh[nb * 2 + 1][1] = r[3];
                ldmx4(r, sb + SM_BLO + byte);
                bl[nb * 2][0] = r[0]; bl[nb * 2 + 1][0] = r[1];
                bl[nb * 2][1] = r[2]; bl[nb * 2 + 1][1] = r[3];
            }
#pragma unroll
            for (int mi = 0; mi < 4; mi++)
#pragma unroll
                for (int ni = 0; ni < 4; ni++) {
                    mma16816(acc[mi][ni], ah[mi], bh[ni]);
                    mma16816(acc[mi][ni], ah[mi], bl[ni]);
                    mma16816(acc[mi][ni], al[mi], bh[ni]);
                }
        }
    }

    // ---- epilogue: fragment regs -> gmem ----
    const int er = lane >> 2;          // 0..7
    const int ec = (lane & 3) * 2;     // 0,2,4,6
#pragma unroll
    for (int mi = 0; mi < 4; mi++) {
#pragma unroll
        for (int ni = 0; ni < 4; ni++) {
            const int r = m0 + warp_m * 64 + mi * 16 + er;
            const int c = n0 + warp_n * 32 + ni * 8 + ec;
            *(float2*)(C + (size_t)r * N + c) =
                make_float2(acc[mi][ni][0], acc[mi][ni][1]);
            *(float2*)(C + (size_t)(r + 8) * N + c) =
                make_float2(acc[mi][ni][2], acc[mi][ni][3]);
        }
    }
}

// ---------------------------------------------------------------------------
// Flash attention, causal. One CTA = one (b, h, 64-row q block).
// (identical math to the 707us passing version; q-block order reversed)
// ---------------------------------------------------------------------------
constexpr int FS = 68;

__global__ __launch_bounds__(256)
void flash_attn(const float* __restrict__ Qp, const float* __restrict__ Kp,
                const float* __restrict__ Vp, float* __restrict__ Op)
{
    extern __shared__ float sm[];
    float* Qs = sm;
    float* Ks = Qs + 64 * FS;
    float* Vs = Ks + 64 * FS;
    float* Ps = Vs + 64 * FS;

    const int tid = threadIdx.x;
    const int tc  = tid & 15;
    const int tr  = tid >> 4;
    const int qb  = gridDim.x - 1 - blockIdx.x;   // longest blocks first
    const int h   = blockIdx.y;
    const int b   = blockIdx.z;

    const size_t head_base = (size_t)b * S_LEN * D_DIM + (size_t)h * DKH;

    const int lr = tid >> 2;
    const int lc = (tid & 3) * 16;

    { // load Q tile
        const float* src = Qp + head_base + (size_t)(qb * 64 + lr) * D_DIM + lc;
        float4 v0 = *(const float4*)(src);
        float4 v1 = *(const float4*)(src + 4);
        float4 v2 = *(const float4*)(src + 8);
        float4 v3 = *(const float4*)(src + 12);
        float* dst = Qs + lr * FS + lc;
        *(float4*)(dst)      = v0;
        *(float4*)(dst + 4)  = v1;
        *(float4*)(dst + 8)  = v2;
        *(float4*)(dst + 12) = v3;
    }

    float m_i[4], l_i[4], o[4][4];
#pragma unroll
    for (int i = 0; i < 4; i++) {
        m_i[i] = -1e30f; l_i[i] = 0.f;
#pragma unroll
        for (int c = 0; c < 4; c++) o[i][c] = 0.f;
    }

    for (int kb = 0; kb <= qb; kb++) {
        __syncthreads();
        {
            const float* ks = Kp + head_base + (size_t)(kb * 64 + lr) * D_DIM + lc;
            const float* vs = Vp + head_base + (size_t)(kb * 64 + lr) * D_DIM + lc;
            float* kd = Ks + lr * FS + lc;
            float* vd = Vs + lr * FS + lc;
            float4 k0 = *(const float4*)(ks);
            float4 k1 = *(const float4*)(ks + 4);
            float4 k2 = *(const float4*)(ks + 8);
            float4 k3 = *(const float4*)(ks + 12);
            *(float4*)(kd) = k0; *(float4*)(kd + 4) = k1;
            *(float4*)(kd + 8) = k2; *(float4*)(kd + 12) = k3;
            float4 v0 = *(const float4*)(vs);
            float4 v1 = *(const float4*)(vs + 4);
            float4 v2 = *(const float4*)(vs + 8);
            float4 v3 = *(const float4*)(vs + 12);
            *(float4*)(vd) = v0; *(float4*)(vd + 4) = v1;
            *(float4*)(vd + 8) = v2; *(float4*)(vd + 12) = v3;
        }
        __syncthreads();

        float sc[4][4];
#pragma unroll
        for (int i = 0; i < 4; i++)
#pragma unroll
            for (int jj = 0; jj < 4; jj++) sc[i][jj] = 0.f;

#pragma unroll 4
        for (int c = 0; c < 64; c += 4) {
            float4 qv[4], kv[4];
#pragma unroll
            for (int i = 0; i < 4; i++)
                qv[i] = *(const float4*)&Qs[(tr * 4 + i) * FS + c];
#pragma unroll
            for (int jj = 0; jj < 4; jj++)
                kv[jj] = *(const float4*)&Ks[(tc + 16 * jj) * FS + c];
#pragma unroll
            for (int i = 0; i < 4; i++)
#pragma unroll
                for (int jj = 0; jj < 4; jj++) {
                    sc[i][jj] += qv[i].x * kv[jj].x;
                    sc[i][jj] += qv[i].y * kv[jj].y;
                    sc[i][jj] += qv[i].z * kv[jj].z;
                    sc[i][jj] += qv[i].w * kv[jj].w;
                }
        }

        const bool diag = (kb == qb);
#pragma unroll
        for (int i = 0; i < 4; i++) {
            const int rloc = tr * 4 + i;
            float mx = -1e30f;
#pragma unroll
            for (int jj = 0; jj < 4; jj++) {
                float s = sc[i][jj] * 0.125f;
                if (diag && (tc + 16 * jj) > rloc) s = -1e30f;
                sc[i][jj] = s;
                mx = fmaxf(mx, s);
            }
            mx = fmaxf(mx, __shfl_xor_sync(0xffffffffu, mx, 1));
            mx = fmaxf(mx, __shfl_xor_sync(0xffffffffu, mx, 2));
            mx = fmaxf(mx, __shfl_xor_sync(0xffffffffu, mx, 4));
            mx = fmaxf(mx, __shfl_xor_sync(0xffffffffu, mx, 8));
            const float mn = fmaxf(m_i[i], mx);
            const float alpha = __expf(m_i[i] - mn);
            m_i[i] = mn;
            float ls = 0.f;
#pragma unroll
            for (int jj = 0; jj < 4; jj++) {
                float p = __expf(sc[i][jj] - mn);
                ls += p;
                Ps[rloc * FS + tc + 16 * jj] = p;
            }
            ls += __shfl_xor_sync(0xffffffffu, ls, 1);
            ls += __shfl_xor_sync(0xffffffffu, ls, 2);
            ls += __shfl_xor_sync(0xffffffffu, ls, 4);
            ls += __shfl_xor_sync(0xffffffffu, ls, 8);
            l_i[i] = l_i[i] * alpha + ls;
#pragma unroll
            for (int c = 0; c < 4; c++) o[i][c] *= alpha;
        }
        __syncthreads();

#pragma unroll 8
        for (int j = 0; j < 64; j++) {
            float pv[4], vv[4];
#pragma unroll
            for (int i = 0; i < 4; i++) pv[i] = Ps[(tr * 4 + i) * FS + j];
#pragma unroll
            for (int c = 0; c < 4; c++) vv[c] = Vs[j * FS + tc + 16 * c];
#pragma unroll
            for (int i = 0; i < 4; i++)
#pragma unroll
                for (int c = 0; c < 4; c++) o[i][c] += pv[i] * vv[c];
        }
    }

#pragma unroll
    for (int i = 0; i < 4; i++) {
        const float inv = 1.f / l_i[i];
        const size_t row = head_base + (size_t)(qb * 64 + tr * 4 + i) * D_DIM;
#pragma unroll
        for (int c = 0; c < 4; c++)
            Op[row + tc + 16 * c] = o[i][c] * inv;
    }
}

// ---------------------------------------------------------------------------
// launch
// ---------------------------------------------------------------------------
extern "C" void kernel_launch(void* const* d_in, const int* in_sizes, int n_in,
                              void* d_out, int out_size)
{
    const float* query = (const float*)d_in[0];
    const float* key   = (const float*)d_in[1];
    const float* value = (const float*)d_in[2];
    const float* Wq    = (const float*)d_in[3];
    const float* Wk    = (const float*)d_in[4];
    const float* Wv    = (const float*)d_in[5];
    const float* Wo    = (const float*)d_in[6];
    float* out = (float*)d_out;

    float *qp, *kp, *vp, *xp;
    cudaGetSymbolAddress((void**)&qp, g_Q);
    cudaGetSymbolAddress((void**)&kp, g_K);
    cudaGetSymbolAddress((void**)&vp, g_V);
    cudaGetSymbolAddress((void**)&xp, g_X);

    const int M = B_SZ * S_LEN;   // 4096
    const int N = D_DIM, K = D_DIM;

    cudaFuncSetAttribute(gemm_mma, cudaFuncAttributeMaxDynamicSharedMemorySize,
                         SM_GEMM_TOTAL);
    dim3 ggrid(N / 128, M / 128);   // (8, 32)

    gemm_mma<<<ggrid, 256, SM_GEMM_TOTAL>>>(query, Wq, qp, M, N, K);
    gemm_mma<<<ggrid, 256, SM_GEMM_TOTAL>>>(key,   Wk, kp, M, N, K);
    gemm_mma<<<ggrid, 256, SM_GEMM_TOTAL>>>(value, Wv, vp, M, N, K);

    const size_t fsmem = 4 * 64 * FS * sizeof(float);  // 69632 B
    cudaFuncSetAttribute(flash_attn, cudaFuncAttributeMaxDynamicSharedMemorySize,
                         (int)fsmem);
    dim3 fgrid(S_LEN / 64, H_NUM, B_SZ);
    flash_attn<<<fgrid, 256, fsmem>>>(qp, kp, vp, xp);

    gemm_mma<<<ggrid, 256, SM_GEMM_TOTAL>>>(xp, Wo, out, M, N, K);
}

// round 4
// speedup vs baseline: 2.5909x; 1.6769x over previous
#include <cuda_runtime.h>
#include <cuda_bf16.h>
#include <math.h>
#include <stdint.h>

#define B_SZ  2
#define S_LEN 2048
#define D_DIM 1024
#define H_NUM 16
#define DKH   64

// Scratch (allocation-free rule: __device__ globals)
__device__ float g_Q[B_SZ * S_LEN * D_DIM];
__device__ float g_K[B_SZ * S_LEN * D_DIM];
__device__ float g_V[B_SZ * S_LEN * D_DIM];
__device__ float g_X[B_SZ * S_LEN * D_DIM];

// ===========================================================================
// helpers (baseline ISA only: ldmatrix sm_75+, mma.sync bf16 sm_80+)
// ===========================================================================
__device__ __forceinline__ uint32_t smem_u32(const void* p) {
    uint32_t a;
    asm("{ .reg .u64 t; cvta.to.shared.u64 t, %1; cvt.u32.u64 %0, t; }"
        : "=r"(a) : "l"(p));
    return a;
}

__device__ __forceinline__ void ldmx4(uint32_t* r, uint32_t addr) {
    asm volatile("ldmatrix.sync.aligned.m8n8.x4.shared.b16 {%0,%1,%2,%3}, [%4];"
                 : "=r"(r[0]), "=r"(r[1]), "=r"(r[2]), "=r"(r[3]) : "r"(addr));
}

__device__ __forceinline__ void ldmx4t(uint32_t* r, uint32_t addr) {
    asm volatile("ldmatrix.sync.aligned.m8n8.x4.trans.shared.b16 {%0,%1,%2,%3}, [%4];"
                 : "=r"(r[0]), "=r"(r[1]), "=r"(r[2]), "=r"(r[3]) : "r"(addr));
}

__device__ __forceinline__ void mma16816(float* c, const uint32_t* a,
                                         uint32_t b0, uint32_t b1) {
    asm volatile(
        "mma.sync.aligned.m16n8k16.row.col.f32.bf16.bf16.f32 "
        "{%0,%1,%2,%3}, {%4,%5,%6,%7}, {%8,%9}, {%0,%1,%2,%3};"
        : "+f"(c[0]), "+f"(c[1]), "+f"(c[2]), "+f"(c[3])
        : "r"(a[0]), "r"(a[1]), "r"(a[2]), "r"(a[3]), "r"(b0), "r"(b1));
}

__device__ __forceinline__ uint32_t packbf(float x, float y) {
    __nv_bfloat162 h = __float22bfloat162_rn(make_float2(x, y));
    return *(uint32_t*)&h;
}

// ===========================================================================
// Tensor-core GEMM (NT): C[M,N] = A[M,K] @ W[N,K]^T, fp32 via 3-term bf16
// split. (unchanged from passing Round-3 kernel)
// ===========================================================================
constexpr int SAS     = 72;
constexpr int SASB    = SAS * 2;       // 144 bytes
constexpr int TILE_B  = 128 * SASB;    // 18432
constexpr int SM_AHI  = 0;
constexpr int SM_ALO  = TILE_B;
constexpr int SM_BHI  = 2 * TILE_B;
constexpr int SM_BLO  = 3 * TILE_B;
constexpr int SM_GEMM_TOTAL = 4 * TILE_B;   // 73728
constexpr int TBK     = 64;
constexpr int STAGES  = D_DIM / TBK;   // 16

__global__ __launch_bounds__(256, 1)
void gemm_mma(const float* __restrict__ A, const float* __restrict__ W,
              float* __restrict__ C, int M, int N, int K)
{
    extern __shared__ char smc[];
    const uint32_t sb = smem_u32(smc);
    const int tid  = threadIdx.x;
    const int wid  = tid >> 5;
    const int lane = tid & 31;
    const int warp_m = wid & 1;
    const int warp_n = wid >> 1;
    const int m0 = blockIdx.y * 128;
    const int n0 = blockIdx.x * 128;

    float acc[4][4][4];
#pragma unroll
    for (int mi = 0; mi < 4; mi++)
#pragma unroll
        for (int ni = 0; ni < 4; ni++)
#pragma unroll
            for (int q = 0; q < 4; q++) acc[mi][ni][q] = 0.f;

    const bool isA = tid < 128;
    const int  t   = tid & 127;
    const float* src = isA ? (A + (size_t)m0 * K) : (W + (size_t)n0 * K);
    char* hi_p = smc + (isA ? SM_AHI : SM_BHI);
    char* lo_p = smc + (isA ? SM_ALO : SM_BLO);

    const int lr  = lane & 15;
    const int lkb = (lane >> 4) << 4;

    for (int s = 0; s < STAGES; s++) {
        __syncthreads();
        const float* s_src = src + s * TBK;
#pragma unroll 4
        for (int i = 0; i < 16; i++) {
            const int chunk = t + (i << 7);
            const int row = chunk >> 4;
            const int ch  = chunk & 15;
            const float4 v = *(const float4*)(s_src + (size_t)row * K + (ch << 2));

            __nv_bfloat162 h01 = __float22bfloat162_rn(make_float2(v.x, v.y));
            __nv_bfloat162 h23 = __float22bfloat162_rn(make_float2(v.z, v.w));
            float2 f01 = __bfloat1622float2(h01);
            float2 f23 = __bfloat1622float2(h23);
            __nv_bfloat162 l01 =
                __float22bfloat162_rn(make_float2(v.x - f01.x, v.y - f01.y));
            __nv_bfloat162 l23 =
                __float22bfloat162_rn(make_float2(v.z - f23.x, v.w - f23.y));

            uint2 uh, ul;
            uh.x = *(uint32_t*)&h01; uh.y = *(uint32_t*)&h23;
            ul.x = *(uint32_t*)&l01; ul.y = *(uint32_t*)&l23;

            const uint32_t off = row * SASB + (ch << 3);
            *(uint2*)(hi_p + off) = uh;
            *(uint2*)(lo_p + off) = ul;
        }
        __syncthreads();

#pragma unroll
        for (int ks = 0; ks < 4; ks++) {
            const uint32_t kb = ks * 32 + lkb;
            uint32_t ah[4][4], al[4][4];
#pragma unroll
            for (int mi = 0; mi < 4; mi++) {
                const uint32_t row = warp_m * 64 + mi * 16 + lr;
                const uint32_t byte = row * SASB + kb;
                ldmx4(ah[mi], sb + SM_AHI + byte);
                ldmx4(al[mi], sb + SM_ALO + byte);
            }
            uint32_t bh[4][2], bl[4][2];
#pragma unroll
            for (int nb = 0; nb < 2; nb++) {
                const uint32_t row = warp_n * 32 + nb * 16 + lr;
                const uint32_t byte = row * SASB + kb;
                uint32_t r[4];
                ldmx4(r, sb + SM_BHI + byte);
                bh[nb * 2][0] = r[0]; bh[nb * 2 + 1][0] = r[1];
                bh[nb * 2][1] = r[2]; bh[nb * 2 + 1][1] = r[3];
                ldmx4(r, sb + SM_BLO + byte);
                bl[nb * 2][0] = r[0]; bl[nb * 2 + 1][0] = r[1];
                bl[nb * 2][1] = r[2]; bl[nb * 2 + 1][1] = r[3];
            }
#pragma unroll
            for (int mi = 0; mi < 4; mi++)
#pragma unroll
                for (int ni = 0; ni < 4; ni++) {
                    mma16816(acc[mi][ni], ah[mi], bh[ni][0], bh[ni][1]);
                    mma16816(acc[mi][ni], ah[mi], bl[ni][0], bl[ni][1]);
                    mma16816(acc[mi][ni], al[mi], bh[ni][0], bh[ni][1]);
                }
        }
    }

    const int er = lane >> 2;
    const int ec = (lane & 3) * 2;
#pragma unroll
    for (int mi = 0; mi < 4; mi++) {
#pragma unroll
        for (int ni = 0; ni < 4; ni++) {
            const int r = m0 + warp_m * 64 + mi * 16 + er;
            const int c = n0 + warp_n * 32 + ni * 8 + ec;
            *(float2*)(C + (size_t)r * N + c) =
                make_float2(acc[mi][ni][0], acc[mi][ni][1]);
            *(float2*)(C + (size_t)(r + 8) * N + c) =
                make_float2(acc[mi][ni][2], acc[mi][ni][3]);
        }
    }
}

// ===========================================================================
// Tensor-core flash attention (causal). CTA = 128 q-rows x (b,h).
// 8 warps, warp w owns q-rows [w*16, w*16+16). K/V blocks of 64.
// QK^T and P.V both via mma.sync bf16 with 3-term hi/lo split.
// ===========================================================================
constexpr int FQHI = 0;
constexpr int FQLO = FQHI + 128 * SASB;   // 18432
constexpr int FKHI = FQLO + 128 * SASB;   // 36864
constexpr int FKLO = FKHI + 64 * SASB;    // 46080
constexpr int FVHI = FKLO + 64 * SASB;    // 55296
constexpr int FVLO = FVHI + 64 * SASB;    // 64512
constexpr int FSM_TOTAL = FVLO + 64 * SASB;  // 73728

__global__ __launch_bounds__(256, 1)
void flash_mma(const float* __restrict__ Qp, const float* __restrict__ Kp,
               const float* __restrict__ Vp, float* __restrict__ Op)
{
    extern __shared__ char smc[];
    const uint32_t sb = smem_u32(smc);
    const int tid  = threadIdx.x;
    const int wid  = tid >> 5;
    const int lane = tid & 31;
    const int qb   = gridDim.x - 1 - blockIdx.x;   // longest blocks first
    const int h    = blockIdx.y;
    const int b    = blockIdx.z;

    const size_t head = (size_t)b * S_LEN * D_DIM + (size_t)h * DKH;

    // ---- load Q tile (scaled by 1/sqrt(dk)=0.125 before split) ----
#pragma unroll
    for (int i = 0; i < 8; i++) {
        const int chunk = tid + (i << 8);
        const int row = chunk >> 4;        // 0..127
        const int ch  = chunk & 15;
        float4 v = *(const float4*)(Qp + head + (size_t)(qb * 128 + row) * D_DIM + (ch << 2));
        v.x *= 0.125f; v.y *= 0.125f; v.z *= 0.125f; v.w *= 0.125f;

        __nv_bfloat162 h01 = __float22bfloat162_rn(make_float2(v.x, v.y));
        __nv_bfloat162 h23 = __float22bfloat162_rn(make_float2(v.z, v.w));
        float2 f01 = __bfloat1622float2(h01);
        float2 f23 = __bfloat1622float2(h23);
        __nv_bfloat162 l01 = __float22bfloat162_rn(make_float2(v.x - f01.x, v.y - f01.y));
        __nv_bfloat162 l23 = __float22bfloat162_rn(make_float2(v.z - f23.x, v.w - f23.y));

        const uint32_t off = row * SASB + (ch << 3);
        uint2 uh, ul;
        uh.x = *(uint32_t*)&h01; uh.y = *(uint32_t*)&h23;
        ul.x = *(uint32_t*)&l01; ul.y = *(uint32_t*)&l23;
        *(uint2*)(smc + FQHI + off) = uh;
        *(uint2*)(smc + FQLO + off) = ul;
    }

    float o[8][4];
    float m0r = -1e30f, m1r = -1e30f, l0r = 0.f, l1r = 0.f;
#pragma unroll
    for (int ni = 0; ni < 8; ni++)
#pragma unroll
        for (int q = 0; q < 4; q++) o[ni][q] = 0.f;

    const int lr  = lane & 15;
    const int lkb = (lane >> 4) << 4;
    const int kb_max = 2 * qb + 1;

    for (int kb = 0; kb <= kb_max; kb++) {
        __syncthreads();   // prior iteration done with K/V smem (also covers Q store)
        // ---- load + split K,V blocks (64x64 each) ----
#pragma unroll
        for (int i = 0; i < 4; i++) {
            const int chunk = tid + (i << 8);
            const int row = chunk >> 4;     // 0..63
            const int ch  = chunk & 15;
            const size_t goff = head + (size_t)(kb * 64 + row) * D_DIM + (ch << 2);
            const uint32_t off = row * SASB + (ch << 3);

            float4 v = *(const float4*)(Kp + goff);
            __nv_bfloat162 h01 = __float22bfloat162_rn(make_float2(v.x, v.y));
            __nv_bfloat162 h23 = __float22bfloat162_rn(make_float2(v.z, v.w));
            float2 f01 = __bfloat1622float2(h01);
            float2 f23 = __bfloat1622float2(h23);
            __nv_bfloat162 l01 = __float22bfloat162_rn(make_float2(v.x - f01.x, v.y - f01.y));
            __nv_bfloat162 l23 = __float22bfloat162_rn(make_float2(v.z - f23.x, v.w - f23.y));
            uint2 uh, ul;
            uh.x = *(uint32_t*)&h01; uh.y = *(uint32_t*)&h23;
            ul.x = *(uint32_t*)&l01; ul.y = *(uint32_t*)&l23;
            *(uint2*)(smc + FKHI + off) = uh;
            *(uint2*)(smc + FKLO + off) = ul;

            v = *(const float4*)(Vp + goff);
            h01 = __float22bfloat162_rn(make_float2(v.x, v.y));
            h23 = __float22bfloat162_rn(make_float2(v.z, v.w));
            f01 = __bfloat1622float2(h01);
            f23 = __bfloat1622float2(h23);
            l01 = __float22bfloat162_rn(make_float2(v.x - f01.x, v.y - f01.y));
            l23 = __float22bfloat162_rn(make_float2(v.z - f23.x, v.w - f23.y));
            uh.x = *(uint32_t*)&h01; uh.y = *(uint32_t*)&h23;
            ul.x = *(uint32_t*)&l01; ul.y = *(uint32_t*)&l23;
            *(uint2*)(smc + FVHI + off) = uh;
            *(uint2*)(smc + FVLO + off) = ul;
        }
        __syncthreads();

        // ---- QK^T: scores 16x64 per warp ----
        float sc[8][4];
#pragma unroll
        for (int ni = 0; ni < 8; ni++)
#pragma unroll
            for (int q = 0; q < 4; q++) sc[ni][q] = 0.f;

#pragma unroll
        for (int ks = 0; ks < 4; ks++) {
            const uint32_t abyte = (wid * 16 + lr) * SASB + ks * 32 + lkb;
            uint32_t qh[4], ql[4];
            ldmx4(qh, sb + FQHI + abyte);
            ldmx4(ql, sb + FQLO + abyte);
#pragma unroll
            for (int nb = 0; nb < 4; nb++) {
                const uint32_t bbyte = (nb * 16 + lr) * SASB + ks * 32 + lkb;
                uint32_t kh[4], kl[4];
                ldmx4(kh, sb + FKHI + bbyte);
                ldmx4(kl, sb + FKLO + bbyte);
                mma16816(sc[nb * 2],     qh, kh[0], kh[2]);
                mma16816(sc[nb * 2],     qh, kl[0], kl[2]);
                mma16816(sc[nb * 2],     ql, kh[0], kh[2]);
                mma16816(sc[nb * 2 + 1], qh, kh[1], kh[3]);
                mma16816(sc[nb * 2 + 1], qh, kl[1], kl[3]);
                mma16816(sc[nb * 2 + 1], ql, kh[1], kh[3]);
            }
        }

        // ---- causal mask (only last <=2 k-blocks can clip this warp) ----
        const int q0 = qb * 128 + wid * 16 + (lane >> 2);
        if (kb * 64 + 63 > qb * 128 + wid * 16) {
#pragma unroll
            for (int ni = 0; ni < 8; ni++) {
#pragma unroll
                for (int c = 0; c < 2; c++) {
                    const int col = kb * 64 + ni * 8 + (lane & 3) * 2 + c;
                    if (col > q0)     sc[ni][c]     = -1e30f;
                    if (col > q0 + 8) sc[ni][2 + c] = -1e30f;
                }
            }
        }

        // ---- online softmax on fragments ----
        float mx0 = -1e30f, mx1 = -1e30f;
#pragma unroll
        for (int ni = 0; ni < 8; ni++) {
            mx0 = fmaxf(mx0, fmaxf(sc[ni][0], sc[ni][1]));
            mx1 = fmaxf(mx1, fmaxf(sc[ni][2], sc[ni][3]));
        }
        mx0 = fmaxf(mx0, __shfl_xor_sync(0xffffffffu, mx0, 1));
        mx0 = fmaxf(mx0, __shfl_xor_sync(0xffffffffu, mx0, 2));
        mx1 = fmaxf(mx1, __shfl_xor_sync(0xffffffffu, mx1, 1));
        mx1 = fmaxf(mx1, __shfl_xor_sync(0xffffffffu, mx1, 2));

        const float mn0 = fmaxf(m0r, mx0);
        const float mn1 = fmaxf(m1r, mx1);
        const float al0 = __expf(m0r - mn0);
        const float al1 = __expf(m1r - mn1);
        m0r = mn0; m1r = mn1;

        float ls0 = 0.f, ls1 = 0.f;
#pragma unroll
        for (int ni = 0; ni < 8; ni++) {
            sc[ni][0] = __expf(sc[ni][0] - mn0); ls0 += sc[ni][0];
            sc[ni][1] = __expf(sc[ni][1] - mn0); ls0 += sc[ni][1];
            sc[ni][2] = __expf(sc[ni][2] - mn1); ls1 += sc[ni][2];
            sc[ni][3] = __expf(sc[ni][3] - mn1); ls1 += sc[ni][3];
        }
        ls0 += __shfl_xor_sync(0xffffffffu, ls0, 1);
        ls0 += __shfl_xor_sync(0xffffffffu, ls0, 2);
        ls1 += __shfl_xor_sync(0xffffffffu, ls1, 1);
        ls1 += __shfl_xor_sync(0xffffffffu, ls1, 2);
        l0r = l0r * al0 + ls0;
        l1r = l1r * al1 + ls1;
#pragma unroll
        for (int ni = 0; ni < 8; ni++) {
            o[ni][0] *= al0; o[ni][1] *= al0;
            o[ni][2] *= al1; o[ni][3] *= al1;
        }

        // ---- P.V (P from score fragments, split hi/lo in registers) ----
#pragma unroll
        for (int ks = 0; ks < 4; ks++) {
            uint32_t ph[4], pl[4];
            {
                const float p0 = sc[2 * ks][0],     p1 = sc[2 * ks][1];
                const float p2 = sc[2 * ks][2],     p3 = sc[2 * ks][3];
                const float p4 = sc[2 * ks + 1][0], p5 = sc[2 * ks + 1][1];
                const float p6 = sc[2 * ks + 1][2], p7 = sc[2 * ks + 1][3];
                ph[0] = packbf(p0, p1); ph[1] = packbf(p2, p3);
                ph[2] = packbf(p4, p5); ph[3] = packbf(p6, p7);
                __nv_bfloat162 t;
                float2 f;
                t = *(__nv_bfloat162*)&ph[0]; f = __bfloat1622float2(t);
                pl[0] = packbf(p0 - f.x, p1 - f.y);
                t = *(__nv_bfloat162*)&ph[1]; f = __bfloat1622float2(t);
                pl[1] = packbf(p2 - f.x, p3 - f.y);
                t = *(__nv_bfloat162*)&ph[2]; f = __bfloat1622float2(t);
                pl[2] = packbf(p4 - f.x, p5 - f.y);
                t = *(__nv_bfloat162*)&ph[3]; f = __bfloat1622float2(t);
                pl[3] = packbf(p6 - f.x, p7 - f.y);
            }
#pragma unroll
            for (int nt = 0; nt < 4; nt++) {
                const uint32_t vbyte =
                    (ks * 16 + ((lane >> 3) & 1) * 8 + (lane & 7)) * SASB +
                    nt * 32 + ((lane >> 4) << 4);
                uint32_t vh[4], vl[4];
                ldmx4t(vh, sb + FVHI + vbyte);
                ldmx4t(vl, sb + FVLO + vbyte);
                mma16816(o[nt * 2],     ph, vh[0], vh[1]);
                mma16816(o[nt * 2],     ph, vl[0], vl[1]);
                mma16816(o[nt * 2],     pl, vh[0], vh[1]);
                mma16816(o[nt * 2 + 1], ph, vh[2], vh[3]);
                mma16816(o[nt * 2 + 1], ph, vl[2], vl[3]);
                mma16816(o[nt * 2 + 1], pl, vh[2], vh[3]);
            }
        }
    }

    // ---- epilogue ----
    const float inv0 = 1.f / l0r;
    const float inv1 = 1.f / l1r;
    const int r0 = qb * 128 + wid * 16 + (lane >> 2);
    const int ec = (lane & 3) * 2;
#pragma unroll
    for (int ni = 0; ni < 8; ni++) {
        const size_t c = head + (size_t)ni * 8 + ec;
        *(float2*)(Op + c + (size_t)r0 * D_DIM) =
            make_float2(o[ni][0] * inv0, o[ni][1] * inv0);
        *(float2*)(Op + c + (size_t)(r0 + 8) * D_DIM) =
            make_float2(o[ni][2] * inv1, o[ni][3] * inv1);
    }
}

// ---------------------------------------------------------------------------
// launch
// ---------------------------------------------------------------------------
extern "C" void kernel_launch(void* const* d_in, const int* in_sizes, int n_in,
                              void* d_out, int out_size)
{
    const float* query = (const float*)d_in[0];
    const float* key   = (const float*)d_in[1];
    const float* value = (const float*)d_in[2];
    const float* Wq    = (const float*)d_in[3];
    const float* Wk    = (const float*)d_in[4];
    const float* Wv    = (const float*)d_in[5];
    const float* Wo    = (const float*)d_in[6];
    float* out = (float*)d_out;

    float *qp, *kp, *vp, *xp;
    cudaGetSymbolAddress((void**)&qp, g_Q);
    cudaGetSymbolAddress((void**)&kp, g_K);
    cudaGetSymbolAddress((void**)&vp, g_V);
    cudaGetSymbolAddress((void**)&xp, g_X);

    const int M = B_SZ * S_LEN;   // 4096
    const int N = D_DIM, K = D_DIM;

    cudaFuncSetAttribute(gemm_mma, cudaFuncAttributeMaxDynamicSharedMemorySize,
                         SM_GEMM_TOTAL);
    dim3 ggrid(N / 128, M / 128);   // (8, 32)

    gemm_mma<<<ggrid, 256, SM_GEMM_TOTAL>>>(query, Wq, qp, M, N, K);
    gemm_mma<<<ggrid, 256, SM_GEMM_TOTAL>>>(key,   Wk, kp, M, N, K);
    gemm_mma<<<ggrid, 256, SM_GEMM_TOTAL>>>(value, Wv, vp, M, N, K);

    cudaFuncSetAttribute(flash_mma, cudaFuncAttributeMaxDynamicSharedMemorySize,
                         FSM_TOTAL);
    dim3 fgrid(S_LEN / 128, H_NUM, B_SZ);   // (16, 16, 2)
    flash_mma<<<fgrid, 256, FSM_TOTAL>>>(qp, kp, vp, xp);

    gemm_mma<<<ggrid, 256, SM_GEMM_TOTAL>>>(xp, Wo, out, M, N, K);
}